// round 9
// baseline (speedup 1.0000x reference)
#include <cuda_runtime.h>

#define N 8192
#define ROWS_PER_BLK 64
#define COLS_PER_BLK 1024
#define CB 8      /* column tiles: 8192/1024 */
#define RB 128    /* row tiles:    8192/64   */
#define THREADS 256

// Scratch (no device allocation allowed -> __device__ globals)
__device__ float g_rowpart[CB * N];     // [cb][row]  partial row sums (256 KB)
__device__ float g_colpart[RB * N];     // [rb][col]  partial col sums (4 MiB)
__device__ float g_blocksum[32];
__device__ int   g_cnt_final;           // zero-init; self-resetting

// ---------------------------------------------------------------------------
// Pass 1 (UNCHANGED, proven 43.9us @ 78% DRAM): one block per 64x1024 tile
// -> 1024 blocks. Streaming single read of the 256 MiB matrix.
// ---------------------------------------------------------------------------
__global__ void __launch_bounds__(THREADS)
tile_kernel(const float* __restrict__ flow)
{
    const int cb   = blockIdx.x;          // 0..7
    const int rb   = blockIdx.y;          // 0..127
    const int t    = threadIdx.x;         // 0..255
    const int warp = t >> 5;
    const int lane = t & 31;
    const int row0 = rb * ROWS_PER_BLK;
    const int col0 = cb * COLS_PER_BLK;

    __shared__ float s_row[ROWS_PER_BLK][32];   // [row][warp*4 + sublane] 8 KB

    float4 c0 = make_float4(0.f, 0.f, 0.f, 0.f);

    const float4* base = reinterpret_cast<const float4*>(flow)
                         + (size_t)row0 * (N / 4) + (col0 / 4);

    #pragma unroll 4
    for (int r = 0; r < ROWS_PER_BLK; ++r) {
        float4 a = __ldcs(base + (size_t)r * (N / 4) + t);   // streaming

        c0.x += a.x; c0.y += a.y; c0.z += a.z; c0.w += a.w;

        // partial row reduce: 32 lanes -> 4 partials (3 shuffles)
        float s = (a.x + a.y) + (a.z + a.w);
        s += __shfl_xor_sync(0xffffffffu, s, 16);
        s += __shfl_xor_sync(0xffffffffu, s, 8);
        s += __shfl_xor_sync(0xffffffffu, s, 4);
        if (lane < 4) s_row[r][warp * 4 + lane] = s;
    }

    // Column partials: unique writer per (rb, col) -> plain store, no atomics
    reinterpret_cast<float4*>(g_colpart + (size_t)rb * N + col0)[t] = c0;

    __syncthreads();

    // Row fold: 4 threads per row (aligned 4-lane groups), 8 values each.
    {
        const int r = t >> 2;          // 0..63
        const int j = (t & 3) * 8;     // 0,8,16,24
        float s = ((s_row[r][j]     + s_row[r][j + 1]) +
                   (s_row[r][j + 2] + s_row[r][j + 3])) +
                  ((s_row[r][j + 4] + s_row[r][j + 5]) +
                   (s_row[r][j + 6] + s_row[r][j + 7]));
        s += __shfl_xor_sync(0xffffffffu, s, 2);
        s += __shfl_xor_sync(0xffffffffu, s, 1);
        if ((t & 3) == 0) g_rowpart[cb * N + row0 + r] = s;
    }
}

// ---------------------------------------------------------------------------
// Pass 2 (single epilogue): 32 blocks x 1024 threads. 4 threads per column
// (sub = t>>8), each folds 32 rb-partials with independent coalesced loads.
// smem folds the 4 sub-partials, sub0 adds rowparts, |.|, block tree reduce;
// counter-gated last block folds 32 scalars -> out. Fixed-order FP sums and
// integer-only atomics -> bitwise deterministic; counter self-resets.
// ---------------------------------------------------------------------------
__global__ void __launch_bounds__(1024)
epilogue_kernel(float* __restrict__ out)
{
    const int t   = threadIdx.x;          // 0..1023
    const int c   = t & 255;              // column within group
    const int sub = t >> 8;               // 0..3
    const int i   = blockIdx.x * 256 + c; // global column

    float cs = 0.f;
    #pragma unroll
    for (int j = 0; j < RB / 4; ++j)
        cs += g_colpart[(size_t)(sub * (RB / 4) + j) * N + i];

    __shared__ float s_cs[3][256];
    if (sub) s_cs[sub - 1][c] = cs;
    __syncthreads();

    float v = 0.f;
    if (sub == 0) {
        float rs = 0.f;
        #pragma unroll
        for (int cb = 0; cb < CB; ++cb) rs += g_rowpart[cb * N + i];

        float total = (cs + s_cs[0][c]) + (s_cs[1][c] + s_cs[2][c]);
        v = fabsf(rs - total);
        v += __shfl_xor_sync(0xffffffffu, v, 16);
        v += __shfl_xor_sync(0xffffffffu, v, 8);
        v += __shfl_xor_sync(0xffffffffu, v, 4);
        v += __shfl_xor_sync(0xffffffffu, v, 2);
        v += __shfl_xor_sync(0xffffffffu, v, 1);
    }

    __shared__ float sw[8];
    if (sub == 0 && (t & 31) == 0) sw[t >> 5] = v;
    __syncthreads();

    __shared__ int s_fin;
    if (t == 0) {
        float w = ((sw[0] + sw[1]) + (sw[2] + sw[3]))
                + ((sw[4] + sw[5]) + (sw[6] + sw[7]));
        g_blocksum[blockIdx.x] = w;
        __threadfence();
        s_fin = (atomicAdd(&g_cnt_final, 1) == 31);
    }
    __syncthreads();
    if (!s_fin) return;
    __threadfence();

    if (t < 32) {
        float v2 = g_blocksum[t];
        v2 += __shfl_xor_sync(0xffffffffu, v2, 16);
        v2 += __shfl_xor_sync(0xffffffffu, v2, 8);
        v2 += __shfl_xor_sync(0xffffffffu, v2, 4);
        v2 += __shfl_xor_sync(0xffffffffu, v2, 2);
        v2 += __shfl_xor_sync(0xffffffffu, v2, 1);
        if (t == 0) {
            out[0] = v2;
            g_cnt_final = 0;   // reset for next graph replay
        }
    }
}

extern "C" void kernel_launch(void* const* d_in, const int* in_sizes, int n_in,
                              void* d_out, int out_size)
{
    (void)in_sizes; (void)n_in; (void)out_size;
    const float* flow = (const float*)d_in[0];
    float* out = (float*)d_out;

    tile_kernel<<<dim3(CB, RB), THREADS>>>(flow);
    epilogue_kernel<<<32, 1024>>>(out);
}

// round 10
// speedup vs baseline: 1.0052x; 1.0052x over previous
#include <cuda_runtime.h>

#define N 8192
#define ROWS_PER_BLK 64
#define COLS_PER_BLK 1024
#define CB 8      /* column tiles: 8192/1024 */
#define RB 128    /* row tiles:    8192/64   */
#define THREADS 256
#define EBLK 128  /* epilogue blocks */

// Scratch (no device allocation allowed -> __device__ globals)
__device__ float g_rowpart[CB * N];     // [cb][row]  partial row sums (256 KB)
__device__ float g_colpart[RB * N];     // [rb][col]  partial col sums (4 MiB)
__device__ float g_blocksum[EBLK];
__device__ int   g_cnt_final;           // zero-init; self-resetting

// ---------------------------------------------------------------------------
// Pass 1 (UNCHANGED, proven 43.9us @ 78% DRAM): one block per 64x1024 tile
// -> 1024 blocks. Streaming single read of the 256 MiB matrix.
// ---------------------------------------------------------------------------
__global__ void __launch_bounds__(THREADS)
tile_kernel(const float* __restrict__ flow)
{
    const int cb   = blockIdx.x;          // 0..7
    const int rb   = blockIdx.y;          // 0..127
    const int t    = threadIdx.x;         // 0..255
    const int warp = t >> 5;
    const int lane = t & 31;
    const int row0 = rb * ROWS_PER_BLK;
    const int col0 = cb * COLS_PER_BLK;

    __shared__ float s_row[ROWS_PER_BLK][32];   // [row][warp*4 + sublane] 8 KB

    float4 c0 = make_float4(0.f, 0.f, 0.f, 0.f);

    const float4* base = reinterpret_cast<const float4*>(flow)
                         + (size_t)row0 * (N / 4) + (col0 / 4);

    #pragma unroll 4
    for (int r = 0; r < ROWS_PER_BLK; ++r) {
        float4 a = __ldcs(base + (size_t)r * (N / 4) + t);   // streaming

        c0.x += a.x; c0.y += a.y; c0.z += a.z; c0.w += a.w;

        // partial row reduce: 32 lanes -> 4 partials (3 shuffles)
        float s = (a.x + a.y) + (a.z + a.w);
        s += __shfl_xor_sync(0xffffffffu, s, 16);
        s += __shfl_xor_sync(0xffffffffu, s, 8);
        s += __shfl_xor_sync(0xffffffffu, s, 4);
        if (lane < 4) s_row[r][warp * 4 + lane] = s;
    }

    // Column partials: unique writer per (rb, col) -> plain store, no atomics
    reinterpret_cast<float4*>(g_colpart + (size_t)rb * N + col0)[t] = c0;

    __syncthreads();

    // Row fold: 4 threads per row (aligned 4-lane groups), 8 values each.
    {
        const int r = t >> 2;          // 0..63
        const int j = (t & 3) * 8;     // 0,8,16,24
        float s = ((s_row[r][j]     + s_row[r][j + 1]) +
                   (s_row[r][j + 2] + s_row[r][j + 3])) +
                  ((s_row[r][j + 4] + s_row[r][j + 5]) +
                   (s_row[r][j + 6] + s_row[r][j + 7]));
        s += __shfl_xor_sync(0xffffffffu, s, 2);
        s += __shfl_xor_sync(0xffffffffu, s, 1);
        if ((t & 3) == 0) g_rowpart[cb * N + row0 + r] = s;
    }
}

// ---------------------------------------------------------------------------
// Pass 2 (single epilogue, 128 blocks x 256 threads):
//   Block b owns 64 columns (16 float4-cols). Threads = 16 fc x 16 subs;
//   each thread folds 8 rb-partials as 8 INDEPENDENT float4 loads (high MLP,
//   coalesced). smem folds the 16 sub-partials per fc (fixed order), lanes
//   0..15 add the 8 rowpart float4s, |.|, warp reduce -> g_blocksum[b].
//   Counter-gated last block folds 128 scalars -> out; counter self-resets.
//   Integer-only atomics + fixed-order FP -> bitwise deterministic.
// ---------------------------------------------------------------------------
__global__ void __launch_bounds__(256)
epilogue_kernel(float* __restrict__ out)
{
    const int t   = threadIdx.x;          // 0..255
    const int fcl = t & 15;               // float4-col within block: 0..15
    const int sub = t >> 4;               // 0..15
    const int fc  = blockIdx.x * 16 + fcl;  // global float4-col: 0..2047

    const float4* cp = reinterpret_cast<const float4*>(g_colpart);

    float4 cs = make_float4(0.f, 0.f, 0.f, 0.f);
    #pragma unroll
    for (int j = 0; j < RB / 16; ++j) {
        float4 a = cp[(size_t)(sub * (RB / 16) + j) * (N / 4) + fc];
        cs.x += a.x; cs.y += a.y; cs.z += a.z; cs.w += a.w;
    }

    __shared__ float4 s_part[16][17];     // [sub][fc] padded
    s_part[sub][fcl] = cs;
    __syncthreads();

    float v = 0.f;
    if (t < 16) {
        // fold 16 sub-partials for float4-col (blockIdx.x*16 + t), fixed order
        float4 tot = make_float4(0.f, 0.f, 0.f, 0.f);
        #pragma unroll
        for (int s2 = 0; s2 < 16; ++s2) {
            float4 a = s_part[s2][t];
            tot.x += a.x; tot.y += a.y; tot.z += a.z; tot.w += a.w;
        }
        // row sums for the same 4 columns
        const int myfc = blockIdx.x * 16 + t;
        float4 rs = make_float4(0.f, 0.f, 0.f, 0.f);
        #pragma unroll
        for (int cb = 0; cb < CB; ++cb) {
            float4 a = reinterpret_cast<const float4*>(g_rowpart + cb * N)[myfc];
            rs.x += a.x; rs.y += a.y; rs.z += a.z; rs.w += a.w;
        }
        v = (fabsf(rs.x - tot.x) + fabsf(rs.y - tot.y))
          + (fabsf(rs.z - tot.z) + fabsf(rs.w - tot.w));
    }

    if (t < 32) {
        v += __shfl_xor_sync(0xffffffffu, v, 8);
        v += __shfl_xor_sync(0xffffffffu, v, 4);
        v += __shfl_xor_sync(0xffffffffu, v, 2);
        v += __shfl_xor_sync(0xffffffffu, v, 1);
        if (t == 0) g_blocksum[blockIdx.x] = v;
    }

    // gate: last block folds the 128 block sums
    __threadfence();
    __syncthreads();
    __shared__ int s_fin;
    if (t == 0) s_fin = (atomicAdd(&g_cnt_final, 1) == EBLK - 1);
    __syncthreads();
    if (!s_fin) return;
    __threadfence();

    float w = (t < EBLK) ? g_blocksum[t] : 0.f;
    w += __shfl_xor_sync(0xffffffffu, w, 16);
    w += __shfl_xor_sync(0xffffffffu, w, 8);
    w += __shfl_xor_sync(0xffffffffu, w, 4);
    w += __shfl_xor_sync(0xffffffffu, w, 2);
    w += __shfl_xor_sync(0xffffffffu, w, 1);

    __shared__ float sw[8];
    if ((t & 31) == 0) sw[t >> 5] = w;
    __syncthreads();

    if (t == 0) {
        float w2 = ((sw[0] + sw[1]) + (sw[2] + sw[3]))
                 + ((sw[4] + sw[5]) + (sw[6] + sw[7]));
        out[0] = w2;
        g_cnt_final = 0;   // reset for next graph replay
    }
}

extern "C" void kernel_launch(void* const* d_in, const int* in_sizes, int n_in,
                              void* d_out, int out_size)
{
    (void)in_sizes; (void)n_in; (void)out_size;
    const float* flow = (const float*)d_in[0];
    float* out = (float*)d_out;

    tile_kernel<<<dim3(CB, RB), THREADS>>>(flow);
    epilogue_kernel<<<EBLK, 256>>>(out);
}